// round 5
// baseline (speedup 1.0000x reference)
#include <cuda_runtime.h>
#include <cstdint>

#define TOKENS   16384
#define KDIM     4096
#define NOUT     24
#define KC       256
#define NCHUNK   (KDIM / KC)        // 16
#define MT       8                  // tokens per warp
#define WARPS    4
#define THREADS  128
#define TPC      (WARPS * MT)       // 32 tokens per CTA
#define WSTRIDE  272                // padded smem row stride (floats); 272 % 32 == 16 -> conflict-free
#define BUFSZ    (NOUT * WSTRIDE)   // floats per buffer

// Fused weights in SLOT order: g_Wf[q][k], q = r*8+g (r=0..2, g=0..7):
//  r=0: g<4 -> g * W_pre[g] ; g>=4 -> g * W_post[g-4]
//  r=1: g<4 -> res row (g,0) = W_res[4g]   ; g>=4 -> res (g-4,2) = W_res[4(g-4)+2]
//  r=2: g<4 -> res row (g,1) = W_res[4g+1] ; g>=4 -> res (g-4,3) = W_res[4(g-4)+3]
__device__ __align__(16) float g_Wf[NOUT * KDIM];

__global__ void prep_kernel(const float* __restrict__ g,
                            const float* __restrict__ Wpre,
                            const float* __restrict__ Wpost,
                            const float* __restrict__ Wres) {
    int idx = blockIdx.x * blockDim.x + threadIdx.x;
    if (idx >= NOUT * KDIM) return;
    int q = idx >> 12;            // / 4096
    int k = idx & (KDIM - 1);
    int r  = q >> 3;
    int gg = q & 7;
    int gl = gg & 3;
    float w;
    if (r == 0) {
        w = (gg < 4) ? Wpre[gl * KDIM + k] : Wpost[gl * KDIM + k];
    } else {
        int j = (r - 1) + ((gg < 4) ? 0 : 2);   // res element (gl, j) -> W_res row 4*gl + j
        w = Wres[(4 * gl + j) * KDIM + k];
    }
    g_Wf[idx] = g[k] * w;
}

__device__ __forceinline__ void cp_async16(uint32_t smem_dst, const void* gmem_src) {
    asm volatile("cp.async.cg.shared.global [%0], [%1], 16;\n" :: "r"(smem_dst), "l"(gmem_src));
}

// Load one [NOUT][KC] weight tile into padded smem ([24][272]) via cp.async.
// 24*64 = 1536 float4, 12 per thread (128 threads).
__device__ __forceinline__ void load_tile(float* dst, int chunk, int tid) {
    uint32_t dsta = (uint32_t)__cvta_generic_to_shared(dst);
    #pragma unroll
    for (int rr = 0; rr < 12; rr++) {
        int fid = tid + rr * THREADS;        // [0, 1536)
        int q   = fid >> 6;                  // slot row 0..23
        int c4  = fid & 63;                  // float4 col 0..63
        const float4* src = reinterpret_cast<const float4*>(g_Wf + q * KDIM + chunk * KC) + c4;
        cp_async16(dsta + (uint32_t)(q * (WSTRIDE * 4) + c4 * 16), src);
    }
    asm volatile("cp.async.commit_group;\n");
}

// Packed dual FFMA (PTX-only, sm_100+): d.lo += a.lo*b.lo; d.hi += a.hi*b.hi
__device__ __forceinline__ void ffma2(unsigned long long& d,
                                      unsigned long long a,
                                      unsigned long long b) {
    asm("fma.rn.f32x2 %0, %1, %2, %0;" : "+l"(d) : "l"(a), "l"(b));
}

__device__ __forceinline__ float unpack_sum(unsigned long long v) {
    float lo = __uint_as_float((unsigned int)(v & 0xffffffffu));
    float hi = __uint_as_float((unsigned int)(v >> 32));
    return lo + hi;
}

__device__ __forceinline__ float sigmoidf_fast(float h) {
    return 1.0f / (1.0f + __expf(-h));
}

extern __shared__ float smem[];   // 2 * BUFSZ floats = 52224 B

__global__ void __launch_bounds__(THREADS, 3)
mhc_kernel(const float* __restrict__ X,
           const float* __restrict__ b_pre,
           const float* __restrict__ b_post,
           const float* __restrict__ b_res,
           const float* __restrict__ a_pre,
           const float* __restrict__ a_post,
           const float* __restrict__ a_res,
           float* __restrict__ out) {
    const int tid  = threadIdx.x;
    const int lane = tid & 31;
    const int warp = tid >> 5;
    const int g    = lane >> 2;       // lane-group 0..7 (3 weight rows each)
    const int s    = lane & 3;        // K-slice within group
    const int gl   = g & 3;
    const int tok0 = blockIdx.x * TPC + warp * MT;

    unsigned long long acc2[MT][3];
    unsigned long long ss2[MT];
    #pragma unroll
    for (int m = 0; m < MT; m++) {
        ss2[m] = 0ull;
        #pragma unroll
        for (int r = 0; r < 3; r++) acc2[m][r] = 0ull;
    }

    const ulonglong2* X2 = reinterpret_cast<const ulonglong2*>(X);

    float* buf0 = smem;
    float* buf1 = smem + BUFSZ;

    load_tile(buf0, 0, tid);
    asm volatile("cp.async.wait_group 0;\n");
    __syncthreads();

    for (int c = 0; c < NCHUNK; c++) {
        float* cur = (c & 1) ? buf1 : buf0;
        float* nxt = (c & 1) ? buf0 : buf1;
        if (c + 1 < NCHUNK) load_tile(nxt, c + 1, tid);

        const size_t base = (size_t)tok0 * (KDIM / 4) + c * (KC / 4);   // ulonglong2 units

        #pragma unroll 4
        for (int i = 0; i < 16; i++) {
            const int p = i * 4 + s;          // float4 index within chunk [0,64)
            ulonglong2 xv[MT];
            #pragma unroll
            for (int m = 0; m < MT; m++)
                xv[m] = X2[base + (size_t)m * (KDIM / 4) + p];

            #pragma unroll
            for (int r = 0; r < 3; r++) {
                ulonglong2 wv = *reinterpret_cast<const ulonglong2*>(
                    cur + (r * 8 + g) * WSTRIDE + p * 4);
                #pragma unroll
                for (int m = 0; m < MT; m++) {
                    ffma2(acc2[m][r], xv[m].x, wv.x);
                    ffma2(acc2[m][r], xv[m].y, wv.y);
                }
            }
        }

        // Sum of squares: 32-way K-slice per full lane (no group redundancy).
        // Chunk has 64 float4; lane covers {lane, 32+lane}. Fully coalesced, L1-hot.
        #pragma unroll
        for (int m = 0; m < MT; m++) {
            ulonglong2 a = X2[base + (size_t)m * (KDIM / 4) + lane];
            ulonglong2 b = X2[base + (size_t)m * (KDIM / 4) + 32 + lane];
            ffma2(ss2[m], a.x, a.x);
            ffma2(ss2[m], a.y, a.y);
            ffma2(ss2[m], b.x, b.x);
            ffma2(ss2[m], b.y, b.y);
        }

        if (c + 1 < NCHUNK)
            asm volatile("cp.async.wait_group 0;\n");
        __syncthreads();
    }

    // Unpack packed partials
    float acc[MT][3];
    float ss[MT];
    #pragma unroll
    for (int m = 0; m < MT; m++) {
        ss[m] = unpack_sum(ss2[m]);
        #pragma unroll
        for (int r = 0; r < 3; r++) acc[m][r] = unpack_sum(acc2[m][r]);
    }

    // acc: reduce over the 4 in-group K-slices (lane bits 0-1)
    #pragma unroll
    for (int off = 1; off <= 2; off <<= 1) {
        #pragma unroll
        for (int m = 0; m < MT; m++) {
            #pragma unroll
            for (int r = 0; r < 3; r++)
                acc[m][r] += __shfl_xor_sync(0xffffffffu, acc[m][r], off);
        }
    }
    // ss: reduce over all 32 lanes
    #pragma unroll
    for (int off = 1; off <= 16; off <<= 1) {
        #pragma unroll
        for (int m = 0; m < MT; m++)
            ss[m] += __shfl_xor_sync(0xffffffffu, ss[m], off);
    }

    // Extract this lane's two tokens (tA = tok0+s, tB = tok0+4+s) without
    // runtime register indexing.
    float aA[3], aB[3];
    float ssA = 0.0f, ssB = 0.0f;
    #pragma unroll
    for (int m = 0; m < 4; m++) {
        if (s == m) {
            aA[0] = acc[m][0];     aA[1] = acc[m][1];     aA[2] = acc[m][2];
            aB[0] = acc[m + 4][0]; aB[1] = acc[m + 4][1]; aB[2] = acc[m + 4][2];
            ssA = ss[m]; ssB = ss[m + 4];
        }
    }

    const bool preside = (g < 4);
    const int tA = tok0 + s;
    const int tB = tok0 + 4 + s;
    const float rinvA = rsqrtf(ssA * (1.0f / (float)KDIM) + 1e-6f);
    const float rinvB = rsqrtf(ssB * (1.0f / (float)KDIM) + 1e-6f);

    // H_pre (groups 0-3) / H_post (groups 4-7): slot r=0 holds pre/post row gl.
    if (preside) {
        const float ap = a_pre[0];
        const float bp = b_pre[gl];
        out[(size_t)tA * 4 + gl] = sigmoidf_fast(ap * rinvA * aA[0] + bp);
        out[(size_t)tB * 4 + gl] = sigmoidf_fast(ap * rinvB * aB[0] + bp);
    } else {
        const float ap = a_post[0];
        const float bp = b_post[gl];
        out[65536 + (size_t)tA * 4 + gl] = 2.0f * sigmoidf_fast(ap * rinvA * aA[0] + bp);
        out[65536 + (size_t)tB * 4 + gl] = 2.0f * sigmoidf_fast(ap * rinvB * aB[0] + bp);
    }

    // H_res: lane (g,s) owns matrix row gl for ONE token:
    //   g<4 -> token tA, has elements (gl,0),(gl,1) in aA[1],aA[2], gets (gl,2),(gl,3) from lane^16
    //   g>=4 -> token tB, has elements (gl,2),(gl,3) in aB[1],aB[2], gets (gl,0),(gl,1) from lane^16
    const float send1 = preside ? aB[1] : aA[1];
    const float send2 = preside ? aB[2] : aA[2];
    const float x1 = __shfl_xor_sync(0xffffffffu, send1, 16);
    const float x2 = __shfl_xor_sync(0xffffffffu, send2, 16);

    float e[4];
    float myrinv;
    int   myt;
    if (preside) {
        e[0] = aA[1]; e[1] = aA[2]; e[2] = x1; e[3] = x2;
        myrinv = rinvA; myt = tA;
    } else {
        e[0] = x1; e[1] = x2; e[2] = aB[1]; e[3] = aB[2];
        myrinv = rinvB; myt = tB;
    }

    const float aresr = a_res[0] * myrinv;
    #pragma unroll
    for (int j = 0; j < 4; j++) {
        float h = aresr * e[j] + b_res[4 * gl + j];
        h = fminf(fmaxf(h, -15.0f), 15.0f);
        e[j] = __expf(h);
    }

    // Sinkhorn, 20 iterations. Column sums via butterfly over lane bits 2-3
    // (matrix-row index), which stays within this token's 4 lanes.
    #pragma unroll 2
    for (int it = 0; it < 20; it++) {
        #pragma unroll
        for (int j = 0; j < 4; j++) {
            float cs = e[j];
            cs += __shfl_xor_sync(0xffffffffu, cs, 4);
            cs += __shfl_xor_sync(0xffffffffu, cs, 8);
            e[j] *= __fdividef(1.0f, cs + 1e-6f);
        }
        float rs = e[0] + e[1] + e[2] + e[3] + 1e-6f;
        float ri = __fdividef(1.0f, rs);
        e[0] *= ri; e[1] *= ri; e[2] *= ri; e[3] *= ri;
    }

    float4 v;
    v.x = e[0]; v.y = e[1]; v.z = e[2]; v.w = e[3];
    *reinterpret_cast<float4*>(out + 131072 + (size_t)myt * 16 + 4 * gl) = v;
}

extern "C" void kernel_launch(void* const* d_in, const int* in_sizes, int n_in,
                              void* d_out, int out_size) {
    const float* X     = (const float*)d_in[0];
    const float* g     = (const float*)d_in[1];
    const float* Wpre  = (const float*)d_in[2];
    const float* Wpost = (const float*)d_in[3];
    const float* Wres  = (const float*)d_in[4];
    const float* bpre  = (const float*)d_in[5];
    const float* bpost = (const float*)d_in[6];
    const float* bres  = (const float*)d_in[7];
    const float* apre  = (const float*)d_in[8];
    const float* apost = (const float*)d_in[9];
    const float* ares  = (const float*)d_in[10];
    float* out = (float*)d_out;

    prep_kernel<<<(NOUT * KDIM + THREADS - 1) / THREADS, THREADS>>>(g, Wpre, Wpost, Wres);

    const int smem_bytes = 2 * BUFSZ * sizeof(float);   // 52224
    cudaFuncSetAttribute(mhc_kernel, cudaFuncAttributeMaxDynamicSharedMemorySize, smem_bytes);
    mhc_kernel<<<TOKENS / TPC, THREADS, smem_bytes>>>(X, bpre, bpost, bres,
                                                      apre, apost, ares, out);
}

// round 17
// speedup vs baseline: 2.6194x; 2.6194x over previous
#include <cuda_runtime.h>
#include <cstdint>

#define TOKENS   16384
#define KDIM     4096
#define NOUT     24
#define KC       256
#define NCHUNK   (KDIM / KC)        // 16
#define MT       8                  // tokens per warp
#define WARPS    8
#define THREADS  256
#define TPC      (WARPS * MT)       // 64 tokens per CTA
#define GRID     (TOKENS / TPC)     // 256

// smem layout (bytes)
#define XBYTES   (TPC * KC * 4)     // 65536 per buffer
#define WBYTES   (NOUT * KC * 4)    // 24576 per buffer
#define XS_OFF   0
#define WS_OFF   (2 * XBYTES)               // 131072
#define BAR_OFF  (WS_OFF + 2 * WBYTES)      // 180224
#define SMEM_SZ  (BAR_OFF + 64)
#define TXBYTES  (XBYTES + WBYTES)          // 90112

// Chunk-major fused weights: g_Wcm[c][q][kk], q = r*4+grp:
//   r=0: pre row grp; r=1: post row grp; r=2..5: res element (grp, r-2) = W_res row 4*grp+(r-2)
__device__ __align__(16) float g_Wcm[NOUT * KDIM];

__global__ void prep_kernel(const float* __restrict__ g,
                            const float* __restrict__ Wpre,
                            const float* __restrict__ Wpost,
                            const float* __restrict__ Wres) {
    int idx = blockIdx.x * blockDim.x + threadIdx.x;
    if (idx >= NOUT * KDIM) return;
    int c   = idx / (NOUT * KC);
    int rem = idx - c * (NOUT * KC);
    int q   = rem >> 8;            // / 256
    int kk  = rem & (KC - 1);
    int k   = c * KC + kk;
    int r   = q >> 2;
    int grp = q & 3;
    float w;
    if (r == 0)      w = Wpre[grp * KDIM + k];
    else if (r == 1) w = Wpost[grp * KDIM + k];
    else             w = Wres[(4 * grp + (r - 2)) * KDIM + k];
    g_Wcm[idx] = g[k] * w;
}

// Packed dual FFMA (PTX-only): d.lo += a.lo*b.lo; d.hi += a.hi*b.hi
__device__ __forceinline__ void ffma2(unsigned long long& d,
                                      unsigned long long a,
                                      unsigned long long b) {
    asm("fma.rn.f32x2 %0, %1, %2, %0;" : "+l"(d) : "l"(a), "l"(b));
}

__device__ __forceinline__ float unpack_sum(unsigned long long v) {
    float lo = __uint_as_float((unsigned int)(v & 0xffffffffu));
    float hi = __uint_as_float((unsigned int)(v >> 32));
    return lo + hi;
}

__device__ __forceinline__ float sigmoidf_fast(float h) {
    return 1.0f / (1.0f + __expf(-h));
}

__device__ __forceinline__ void bulk_g2s(uint32_t dst, const void* src, int bytes, uint32_t bar) {
    asm volatile(
        "cp.async.bulk.shared::cta.global.mbarrier::complete_tx::bytes [%0], [%1], %2, [%3];"
        :: "r"(dst), "l"(src), "r"(bytes), "r"(bar) : "memory");
}

__device__ __forceinline__ void mbar_wait(uint32_t bar, uint32_t parity) {
    asm volatile(
        "{\n\t"
        ".reg .pred P1;\n\t"
        "WAIT_LOOP_%=:\n\t"
        "mbarrier.try_wait.parity.shared.b64 P1, [%0], %1;\n\t"
        "@P1 bra.uni WAIT_DONE_%=;\n\t"
        "bra.uni WAIT_LOOP_%=;\n\t"
        "WAIT_DONE_%=:\n\t"
        "}"
        :: "r"(bar), "r"(parity) : "memory");
}

extern __shared__ __align__(16) char smem[];

__global__ void __launch_bounds__(THREADS, 1)
mhc_kernel(const float* __restrict__ X,
           const float* __restrict__ b_pre,
           const float* __restrict__ b_post,
           const float* __restrict__ b_res,
           const float* __restrict__ a_pre,
           const float* __restrict__ a_post,
           const float* __restrict__ a_res,
           float* __restrict__ out) {
    const int tid  = threadIdx.x;
    const int lane = tid & 31;
    const int warp = tid >> 5;
    const int grp  = lane >> 3;       // lane-group 0..3 (6 weight rows each)
    const int s    = lane & 7;        // K-slice within group
    const int ctok = blockIdx.x * TPC;
    const int wtok = ctok + warp * MT;

    uint32_t sb;
    asm("{ .reg .u64 t; cvta.to.shared.u64 t, %1; cvt.u32.u64 %0, t; }" : "=r"(sb) : "l"(smem));
    const uint32_t bar0 = sb + BAR_OFF;

    // init mbarriers
    if (tid == 0) {
        asm volatile("mbarrier.init.shared.b64 [%0], 1;" :: "r"(bar0) : "memory");
        asm volatile("mbarrier.init.shared.b64 [%0], 1;" :: "r"(bar0 + 8) : "memory");
        asm volatile("fence.proxy.async.shared::cta;" ::: "memory");
    }
    __syncthreads();

    // Distributed producer: threads 0-63 each copy one X row (1KB), thread 64
    // copies the W block (24KB), thread 0 posts expect_tx (+its single arrival).
    // tx-count ops are commutative within an mbarrier phase, so cross-thread
    // ordering of expect_tx vs completions is safe.
    auto issue_chunk = [&](int c, int b) {
        uint32_t bar = bar0 + b * 8;
        if (tid == 0) {
            asm volatile("mbarrier.arrive.expect_tx.shared.b64 _, [%0], %1;"
                         :: "r"(bar), "r"((uint32_t)TXBYTES) : "memory");
        }
        if (tid < TPC) {
            bulk_g2s(sb + XS_OFF + b * XBYTES + tid * (KC * 4),
                     X + (size_t)(ctok + tid) * KDIM + c * KC,
                     KC * 4, bar);
        } else if (tid == TPC) {
            bulk_g2s(sb + WS_OFF + b * WBYTES,
                     (const char*)g_Wcm + (size_t)c * WBYTES,
                     WBYTES, bar);
        }
    };

    issue_chunk(0, 0);
    issue_chunk(1, 1);

    unsigned long long acc2[MT][6];
    unsigned long long ss2[MT];
    #pragma unroll
    for (int m = 0; m < MT; m++) {
        ss2[m] = 0ull;
        #pragma unroll
        for (int r = 0; r < 6; r++) acc2[m][r] = 0ull;
    }

    for (int c = 0; c < NCHUNK; c++) {
        const int b = c & 1;
        mbar_wait(bar0 + b * 8, (c >> 1) & 1);

        const float* xb = (const float*)(smem + XS_OFF + b * XBYTES) + warp * MT * KC;
        const float* wb = (const float*)(smem + WS_OFF + b * WBYTES);

        #pragma unroll 2
        for (int i = 0; i < 8; i++) {
            const int p4 = (i * 8 + s) * 4;   // float offset of this lane's float4
            ulonglong2 xv[MT];
            #pragma unroll
            for (int m = 0; m < MT; m++)
                xv[m] = *reinterpret_cast<const ulonglong2*>(xb + m * KC + p4);

            #pragma unroll
            for (int r = 0; r < 6; r++) {
                ulonglong2 wv = *reinterpret_cast<const ulonglong2*>(
                    wb + (r * 4 + grp) * KC + p4);
                #pragma unroll
                for (int m = 0; m < MT; m++) {
                    ffma2(acc2[m][r], xv[m].x, wv.x);
                    ffma2(acc2[m][r], xv[m].y, wv.y);
                }
            }
            #pragma unroll
            for (int m = 0; m < MT; m++) {
                ffma2(ss2[m], xv[m].x, xv[m].x);
                ffma2(ss2[m], xv[m].y, xv[m].y);
            }
        }

        __syncthreads();                       // all warps done reading buffer b
        if (c + 2 < NCHUNK)
            issue_chunk(c + 2, b);
    }

    // Unpack packed partials
    float acc[MT][6];
    float ss[MT];
    #pragma unroll
    for (int m = 0; m < MT; m++) {
        ss[m] = unpack_sum(ss2[m]);
        #pragma unroll
        for (int r = 0; r < 6; r++) acc[m][r] = unpack_sum(acc2[m][r]);
    }

    // Reduce over the 8 in-group K-slices (lane bits 0-2)
    #pragma unroll
    for (int off = 1; off <= 4; off <<= 1) {
        #pragma unroll
        for (int m = 0; m < MT; m++) {
            ss[m] += __shfl_xor_sync(0xffffffffu, ss[m], off);
            #pragma unroll
            for (int r = 0; r < 6; r++)
                acc[m][r] += __shfl_xor_sync(0xffffffffu, acc[m][r], off);
        }
    }

    // Lane s takes token wtok+s (compile-time selects)
    float asel[6];
    float sssel = 0.0f;
    #pragma unroll
    for (int m = 0; m < MT; m++) {
        if (s == m) {
            sssel = ss[m];
            #pragma unroll
            for (int r = 0; r < 6; r++) asel[r] = acc[m][r];
        }
    }

    const int t = wtok + s;
    const float rinv = rsqrtf(sssel * (1.0f / (float)KDIM) + 1e-6f);

    // H_pre / H_post: row grp
    out[(size_t)t * 4 + grp] = sigmoidf_fast(a_pre[0] * rinv * asel[0] + b_pre[grp]);
    out[65536 + (size_t)t * 4 + grp] =
        2.0f * sigmoidf_fast(a_post[0] * rinv * asel[1] + b_post[grp]);

    // H_res: this lane owns res matrix row grp (cols 0..3) for token t
    float e[4];
    const float aresr = a_res[0] * rinv;
    #pragma unroll
    for (int j = 0; j < 4; j++) {
        float h = aresr * asel[2 + j] + b_res[4 * grp + j];
        h = fminf(fmaxf(h, -15.0f), 15.0f);
        e[j] = __expf(h);
    }

    // Sinkhorn, 20 iters. Column sums across rows = lane bits 3-4 (offs 8,16):
    // lanes {s, s+8, s+16, s+24} all hold token t, rows 0..3.
    #pragma unroll 2
    for (int it = 0; it < 20; it++) {
        #pragma unroll
        for (int j = 0; j < 4; j++) {
            float cs = e[j];
            cs += __shfl_xor_sync(0xffffffffu, cs, 8);
            cs += __shfl_xor_sync(0xffffffffu, cs, 16);
            e[j] *= __fdividef(1.0f, cs + 1e-6f);
        }
        float rs = e[0] + e[1] + e[2] + e[3] + 1e-6f;
        float ri = __fdividef(1.0f, rs);
        e[0] *= ri; e[1] *= ri; e[2] *= ri; e[3] *= ri;
    }

    float4 v;
    v.x = e[0]; v.y = e[1]; v.z = e[2]; v.w = e[3];
    *reinterpret_cast<float4*>(out + 131072 + (size_t)t * 16 + 4 * grp) = v;
}

extern "C" void kernel_launch(void* const* d_in, const int* in_sizes, int n_in,
                              void* d_out, int out_size) {
    const float* X     = (const float*)d_in[0];
    const float* g     = (const float*)d_in[1];
    const float* Wpre  = (const float*)d_in[2];
    const float* Wpost = (const float*)d_in[3];
    const float* Wres  = (const float*)d_in[4];
    const float* bpre  = (const float*)d_in[5];
    const float* bpost = (const float*)d_in[6];
    const float* bres  = (const float*)d_in[7];
    const float* apre  = (const float*)d_in[8];
    const float* apost = (const float*)d_in[9];
    const float* ares  = (const float*)d_in[10];
    float* out = (float*)d_out;

    prep_kernel<<<(NOUT * KDIM + THREADS - 1) / THREADS, THREADS>>>(g, Wpre, Wpost, Wres);

    cudaFuncSetAttribute(mhc_kernel, cudaFuncAttributeMaxDynamicSharedMemorySize, SMEM_SZ);
    mhc_kernel<<<GRID, THREADS, SMEM_SZ>>>(X, bpre, bpost, bres,
                                           apre, apost, ares, out);
}